// round 3
// baseline (speedup 1.0000x reference)
#include <cuda_runtime.h>

#define NN  100000
#define EE  1200000
#define HIDN 64
#define NHD 4
#define DHD 16
#define NLY 3

// ---- scratch (static device globals: no allocation allowed) ----
__device__ float g_h[NN * HIDN];     // node features between layers
__device__ float g_hw[NN * HIDN];    // per-layer transformed features
__device__ float g_as[NN * NHD];     // attention src terms
__device__ float g_ad[NN * NHD];     // attention dst terms
__device__ float g_den[NN * NHD];    // softmax denominators
__device__ float g_agg[NN * HIDN];   // aggregated messages (numerator)
__device__ float g_c0[NLY * NHD];    // edge-attn constants: a_e = ea*c1 + c0
__device__ float g_c1[NLY * NHD];

// ---------------------------------------------------------------------------
// Precompute c1/c0: edge encoder is rank-1 (EIN=1), so the whole edge path
// collapses to per-(layer,head) scalars.
// ---------------------------------------------------------------------------
__global__ void k_const(const float* __restrict__ w_ee, const float* __restrict__ b_ee,
                        const float* __restrict__ w_eg, const float* __restrict__ att_e)
{
    int l = blockIdx.x, j = threadIdx.x;           // j in [0,64)
    __shared__ float sU[HIDN], sV[HIDN];
    const float* W = w_eg + l * HIDN * HIDN;
    float U = 0.f, V = 0.f;
    for (int k = 0; k < HIDN; k++) {
        float wk = W[k * HIDN + j];
        U += w_ee[k] * wk;
        V += b_ee[k] * wk;
    }
    sU[j] = U; sV[j] = V;
    __syncthreads();
    if (j < NHD) {
        float c1 = 0.f, c0 = 0.f;
        for (int d = 0; d < DHD; d++) {
            float a = att_e[l * HIDN + j * DHD + d];
            c1 += sU[j * DHD + d] * a;
            c0 += sV[j * DHD + d] * a;
        }
        g_c1[l * NHD + j] = c1;
        g_c0[l * NHD + j] = c0;
    }
}

// ---------------------------------------------------------------------------
// Node encoder: h = relu(x @ w1 + b1) @ w2 + b2.  One warp per node,
// 2 output channels per lane, inner GEMM via register shuffle.
// ---------------------------------------------------------------------------
__global__ void k_encode(const float* __restrict__ x,
                         const float* __restrict__ w1, const float* __restrict__ b1,
                         const float* __restrict__ w2, const float* __restrict__ b2)
{
    __shared__ float w2s[HIDN * HIDN];
    int tid = threadIdx.x;
    for (int i = tid; i < HIDN * HIDN / 4; i += blockDim.x)
        ((float4*)w2s)[i] = ((const float4*)w2)[i];
    __syncthreads();

    int warp = tid >> 5, lane = tid & 31;
    int n = blockIdx.x * 8 + warp;
    if (n >= NN) return;

    float xv[6];
    #pragma unroll
    for (int k = 0; k < 6; k++) xv[k] = x[n * 6 + k];

    float h0 = b1[lane], h1 = b1[lane + 32];
    #pragma unroll
    for (int k = 0; k < 6; k++) {
        h0 += xv[k] * w1[k * HIDN + lane];
        h1 += xv[k] * w1[k * HIDN + lane + 32];
    }
    h0 = fmaxf(h0, 0.f); h1 = fmaxf(h1, 0.f);

    float a0 = b2[lane], a1 = b2[lane + 32];
    #pragma unroll
    for (int k = 0; k < HIDN; k++) {
        float hk = (k < 32) ? __shfl_sync(0xffffffffu, h0, k)
                            : __shfl_sync(0xffffffffu, h1, k - 32);
        a0 += hk * w2s[k * HIDN + lane];
        a1 += hk * w2s[k * HIDN + lane + 32];
    }
    g_h[n * HIDN + lane]      = a0;
    g_h[n * HIDN + lane + 32] = a1;
}

// ---------------------------------------------------------------------------
// Per-layer transform: hw = h @ Wg; a_s/a_d head dots; zero agg/den.
// One warp per node.
// ---------------------------------------------------------------------------
__global__ void k_transform(const float* __restrict__ Wg,
                            const float* __restrict__ atts, const float* __restrict__ attd)
{
    __shared__ float ws[HIDN * HIDN];
    __shared__ float s_as[HIDN], s_ad[HIDN];
    int tid = threadIdx.x;
    for (int i = tid; i < HIDN * HIDN / 4; i += blockDim.x)
        ((float4*)ws)[i] = ((const float4*)Wg)[i];
    if (tid < HIDN) { s_as[tid] = atts[tid]; s_ad[tid] = attd[tid]; }
    __syncthreads();

    int warp = tid >> 5, lane = tid & 31;
    int n = blockIdx.x * 8 + warp;
    if (n >= NN) return;

    float h0 = g_h[n * HIDN + lane], h1 = g_h[n * HIDN + lane + 32];
    float a0 = 0.f, a1 = 0.f;
    #pragma unroll
    for (int k = 0; k < HIDN; k++) {
        float hk = (k < 32) ? __shfl_sync(0xffffffffu, h0, k)
                            : __shfl_sync(0xffffffffu, h1, k - 32);
        a0 += hk * ws[k * HIDN + lane];
        a1 += hk * ws[k * HIDN + lane + 32];
    }
    g_hw[n * HIDN + lane]      = a0;
    g_hw[n * HIDN + lane + 32] = a1;

    // head dot products: channel lane -> head lane/16; channel lane+32 -> head 2+lane/16
    float rs0 = a0 * s_as[lane],      rs1 = a1 * s_as[lane + 32];
    float rd0 = a0 * s_ad[lane],      rd1 = a1 * s_ad[lane + 32];
    #pragma unroll
    for (int o = 8; o >= 1; o >>= 1) {
        rs0 += __shfl_xor_sync(0xffffffffu, rs0, o);
        rs1 += __shfl_xor_sync(0xffffffffu, rs1, o);
        rd0 += __shfl_xor_sync(0xffffffffu, rd0, o);
        rd1 += __shfl_xor_sync(0xffffffffu, rd1, o);
    }
    if (lane == 0)  { g_as[n*NHD+0] = rs0; g_as[n*NHD+2] = rs1;
                      g_ad[n*NHD+0] = rd0; g_ad[n*NHD+2] = rd1; }
    if (lane == 16) { g_as[n*NHD+1] = rs0; g_as[n*NHD+3] = rs1;
                      g_ad[n*NHD+1] = rd0; g_ad[n*NHD+3] = rd1; }

    // zero next-stage accumulators (same stream -> ordered before edge kernel)
    g_agg[n * HIDN + lane]      = 0.f;
    g_agg[n * HIDN + lane + 32] = 0.f;
    if (lane < NHD) g_den[n * NHD + lane] = 0.f;
}

// ---------------------------------------------------------------------------
// Fused edge pass: score -> exp -> den atomic, exp*hw[src] -> vector red into
// agg[dst]. One warp handles 2 edges (16 lanes each). hw is L2-resident.
// edge_index arrives as int32 (harness converts int64 -> int32).
// exp(score) directly: max-subtraction is only a stability trick; scores are
// O(1) here, ratio ex/den is mathematically identical.
// ---------------------------------------------------------------------------
__global__ void k_edge(const int* __restrict__ ei, const float* __restrict__ ea, int l)
{
    int gw   = (blockIdx.x * blockDim.x + threadIdx.x) >> 5;
    int lane = threadIdx.x & 31;
    int sub  = lane >> 4, half = lane & 15;
    int e = gw * 2 + sub;
    bool valid = e < EE;

    int src = 0, dst = 0; float eav = 0.f;
    if (valid) {
        src = ei[e];
        dst = ei[EE + e];
        eav = ea[e];
    }

    float ex = 0.f;
    if (valid && half < NHD) {
        float s = g_as[src * NHD + half] + g_ad[dst * NHD + half]
                + eav * g_c1[l * NHD + half] + g_c0[l * NHD + half];
        s = (s > 0.f) ? s : 0.2f * s;          // leaky_relu 0.2
        ex = __expf(s);
        atomicAdd(&g_den[dst * NHD + half], ex);
    }
    // broadcast exp of this lane's head: lanes sub*16 .. sub*16+3 hold heads 0..3
    float exh = __shfl_sync(0xffffffffu, ex, (sub << 4) + (half >> 2));

    if (valid) {
        float4 v = *(const float4*)&g_hw[src * HIDN + half * 4];
        float* p = &g_agg[dst * HIDN + half * 4];
        float mx = exh * v.x, my = exh * v.y, mz = exh * v.z, mw = exh * v.w;
        asm volatile("red.global.add.v4.f32 [%0], {%1,%2,%3,%4};"
                     :: "l"(p), "f"(mx), "f"(my), "f"(mz), "f"(mw) : "memory");
    }
}

// ---------------------------------------------------------------------------
// Finalize: normalize, +bias, ELU, residual, LayerNorm -> h. Warp per node.
// ---------------------------------------------------------------------------
__global__ void k_finalize(int l, const float* __restrict__ b_gat,
                           const float* __restrict__ lng, const float* __restrict__ lnb)
{
    int tid = threadIdx.x, warp = tid >> 5, lane = tid & 31;
    int n = blockIdx.x * 8 + warp;
    if (n >= NN) return;

    float d0 = g_den[n * NHD + (lane >> 4)]     + 1e-16f;
    float d1 = g_den[n * NHD + 2 + (lane >> 4)] + 1e-16f;
    float v0 = g_agg[n * HIDN + lane]      / d0 + b_gat[l * HIDN + lane];
    float v1 = g_agg[n * HIDN + lane + 32] / d1 + b_gat[l * HIDN + lane + 32];
    v0 = (v0 > 0.f) ? v0 : expm1f(v0);          // ELU alpha=1
    v1 = (v1 > 0.f) ? v1 : expm1f(v1);

    float x0 = g_h[n * HIDN + lane]      + v0;
    float x1 = g_h[n * HIDN + lane + 32] + v1;

    float s = x0 + x1;
    #pragma unroll
    for (int o = 16; o; o >>= 1) s += __shfl_xor_sync(0xffffffffu, s, o);
    float m = s * (1.f / 64.f);
    float vv = (x0 - m) * (x0 - m) + (x1 - m) * (x1 - m);
    #pragma unroll
    for (int o = 16; o; o >>= 1) vv += __shfl_xor_sync(0xffffffffu, vv, o);
    float inv = rsqrtf(vv * (1.f / 64.f) + 1e-5f);

    g_h[n * HIDN + lane]      = (x0 - m) * inv * lng[l * HIDN + lane]      + lnb[l * HIDN + lane];
    g_h[n * HIDN + lane + 32] = (x1 - m) * inv * lng[l * HIDN + lane + 32] + lnb[l * HIDN + lane + 32];
}

// ---------------------------------------------------------------------------
// Output projection: out = h @ w_out + b_out
// ---------------------------------------------------------------------------
__global__ void k_out(const float* __restrict__ W, const float* __restrict__ b,
                      float* __restrict__ out)
{
    __shared__ float ws[HIDN * HIDN];
    int tid = threadIdx.x;
    for (int i = tid; i < HIDN * HIDN / 4; i += blockDim.x)
        ((float4*)ws)[i] = ((const float4*)W)[i];
    __syncthreads();

    int warp = tid >> 5, lane = tid & 31;
    int n = blockIdx.x * 8 + warp;
    if (n >= NN) return;

    float h0 = g_h[n * HIDN + lane], h1 = g_h[n * HIDN + lane + 32];
    float a0 = b[lane], a1 = b[lane + 32];
    #pragma unroll
    for (int k = 0; k < HIDN; k++) {
        float hk = (k < 32) ? __shfl_sync(0xffffffffu, h0, k)
                            : __shfl_sync(0xffffffffu, h1, k - 32);
        a0 += hk * ws[k * HIDN + lane];
        a1 += hk * ws[k * HIDN + lane + 32];
    }
    out[n * HIDN + lane]      = a0;
    out[n * HIDN + lane + 32] = a1;
}

// ---------------------------------------------------------------------------
extern "C" void kernel_launch(void* const* d_in, const int* in_sizes, int n_in,
                              void* d_out, int out_size)
{
    const float* x        = (const float*)d_in[0];
    const int*   ei       = (const int*)d_in[1];     // int64 in ref -> int32 on device
    const float* ea       = (const float*)d_in[2];
    const float* w_ne1    = (const float*)d_in[3];
    const float* b_ne1    = (const float*)d_in[4];
    const float* w_ne2    = (const float*)d_in[5];
    const float* b_ne2    = (const float*)d_in[6];
    const float* w_ee     = (const float*)d_in[7];
    const float* b_ee     = (const float*)d_in[8];
    const float* w_gat    = (const float*)d_in[9];
    const float* w_eg     = (const float*)d_in[10];
    const float* att_src  = (const float*)d_in[11];
    const float* att_dst  = (const float*)d_in[12];
    const float* att_edge = (const float*)d_in[13];
    const float* b_gat    = (const float*)d_in[14];
    const float* ln_g     = (const float*)d_in[15];
    const float* ln_b     = (const float*)d_in[16];
    const float* w_out    = (const float*)d_in[17];
    const float* b_out    = (const float*)d_in[18];
    float*       out      = (float*)d_out;

    int nb = (NN + 7) / 8;                 // 8 nodes (warps) per block
    int eb = (EE / 2 + 7) / 8;             // 2 edges per warp, 8 warps per block

    k_const<<<NLY, HIDN>>>(w_ee, b_ee, w_eg, att_edge);
    k_encode<<<nb, 256>>>(x, w_ne1, b_ne1, w_ne2, b_ne2);
    for (int l = 0; l < NLY; l++) {
        k_transform<<<nb, 256>>>(w_gat + l * HIDN * HIDN,
                                 att_src + l * NHD * DHD, att_dst + l * NHD * DHD);
        k_edge<<<eb, 256>>>(ei, ea, l);
        k_finalize<<<nb, 256>>>(l, b_gat, ln_g, ln_b);
    }
    k_out<<<nb, 256>>>(w_out, b_out, out);
}

// round 4
// speedup vs baseline: 1.2114x; 1.2114x over previous
#include <cuda_runtime.h>

#define NN  100000
#define EE  1200000
#define HIDN 64
#define NHD 4
#define DHD 16
#define NLY 3
#define SCAN_B 1024
#define SCAN_G ((NN + SCAN_B - 1) / SCAN_B)   // 98

// ---- scratch (static device globals) ----
__device__ float g_h[NN * HIDN];        // node features between layers
__device__ float g_hw0[NN * HIDN];      // transformed features (ping)
__device__ float g_hw1[NN * HIDN];      // transformed features (pong)
__device__ float g_as0[NN * NHD], g_ad0[NN * NHD];
__device__ float g_as1[NN * NHD], g_ad1[NN * NHD];
__device__ float g_c0[NLY * NHD], g_c1[NLY * NHD];
// CSR by destination
__device__ int   g_deg[NN];
__device__ int   g_rs[NN];
__device__ int   g_cur[NN];
__device__ int   g_csrc[EE];
__device__ float g_cea[EE];
__device__ int   g_psum[SCAN_G];

// ---------------------------------------------------------------------------
// Edge-attn constants (edge encoder is rank-1 since EIN=1):
// a_e[e,h] = ea[e]*c1[l,h] + c0[l,h]
// ---------------------------------------------------------------------------
__global__ void k_const(const float* __restrict__ w_ee, const float* __restrict__ b_ee,
                        const float* __restrict__ w_eg, const float* __restrict__ att_e)
{
    int l = blockIdx.x, j = threadIdx.x;
    __shared__ float sU[HIDN], sV[HIDN];
    const float* W = w_eg + l * HIDN * HIDN;
    float U = 0.f, V = 0.f;
    for (int k = 0; k < HIDN; k++) {
        float wk = W[k * HIDN + j];
        U += w_ee[k] * wk;
        V += b_ee[k] * wk;
    }
    sU[j] = U; sV[j] = V;
    __syncthreads();
    if (j < NHD) {
        float c1 = 0.f, c0 = 0.f;
        for (int d = 0; d < DHD; d++) {
            float a = att_e[l * HIDN + j * DHD + d];
            c1 += sU[j * DHD + d] * a;
            c0 += sV[j * DHD + d] * a;
        }
        g_c1[l * NHD + j] = c1;
        g_c0[l * NHD + j] = c0;
    }
}

// ---------------------------------------------------------------------------
// CSR build: zero deg -> count -> 3-step exclusive scan -> scatter
// ---------------------------------------------------------------------------
__global__ void k_zero()
{
    int i = blockIdx.x * blockDim.x + threadIdx.x;
    if (i < NN) g_deg[i] = 0;
}

__global__ void k_count(const int* __restrict__ ei)
{
    int e = blockIdx.x * blockDim.x + threadIdx.x;
    if (e < EE) atomicAdd(&g_deg[ei[EE + e]], 1);
}

__global__ void k_scan1()
{
    __shared__ int s[SCAN_B];
    int t = threadIdx.x, gid = blockIdx.x * SCAN_B + t;
    int v = (gid < NN) ? g_deg[gid] : 0;
    s[t] = v;
    __syncthreads();
    #pragma unroll
    for (int off = 1; off < SCAN_B; off <<= 1) {
        int u = (t >= off) ? s[t - off] : 0;
        __syncthreads();
        s[t] += u;
        __syncthreads();
    }
    if (gid < NN) g_rs[gid] = s[t] - v;            // exclusive within block
    if (t == SCAN_B - 1) g_psum[blockIdx.x] = s[t];
}

__global__ void k_scan2()
{
    __shared__ int s[SCAN_G];
    int t = threadIdx.x;
    int v = (t < SCAN_G) ? g_psum[t] : 0;
    if (t < SCAN_G) s[t] = v;
    __syncthreads();
    for (int off = 1; off < SCAN_G; off <<= 1) {
        int u = (t >= off && t < SCAN_G) ? s[t - off] : 0;
        __syncthreads();
        if (t < SCAN_G) s[t] += u;
        __syncthreads();
    }
    if (t < SCAN_G) g_psum[t] = s[t] - v;          // exclusive
}

__global__ void k_scan3()
{
    int gid = blockIdx.x * SCAN_B + threadIdx.x;
    if (gid < NN) {
        g_rs[gid] += g_psum[blockIdx.x];
        g_cur[gid] = 0;
    }
}

__global__ void k_scatter(const int* __restrict__ ei, const float* __restrict__ ea)
{
    int e = blockIdx.x * blockDim.x + threadIdx.x;
    if (e >= EE) return;
    int dst = ei[EE + e];
    int pos = g_rs[dst] + atomicAdd(&g_cur[dst], 1);
    g_csrc[pos] = ei[e];
    g_cea[pos]  = ea[e];
}

// ---------------------------------------------------------------------------
// Fused node encoder + layer-0 transform: h = relu(x w1 + b1) w2 + b2;
// hw0 = h @ Wg0; a_s/a_d head dots. One warp per node.
// ---------------------------------------------------------------------------
__global__ void k_encode_t(const float* __restrict__ x,
                           const float* __restrict__ w1, const float* __restrict__ b1,
                           const float* __restrict__ w2, const float* __restrict__ b2,
                           const float* __restrict__ wg0,
                           const float* __restrict__ atts, const float* __restrict__ attd)
{
    __shared__ float w2s[HIDN * HIDN];
    __shared__ float wgs[HIDN * HIDN];
    __shared__ float sa[HIDN], sd[HIDN];
    int tid = threadIdx.x;
    for (int i = tid; i < HIDN * HIDN / 4; i += blockDim.x) {
        ((float4*)w2s)[i] = ((const float4*)w2)[i];
        ((float4*)wgs)[i] = ((const float4*)wg0)[i];
    }
    if (tid < HIDN) { sa[tid] = atts[tid]; sd[tid] = attd[tid]; }
    __syncthreads();

    int warp = tid >> 5, lane = tid & 31;
    int n = blockIdx.x * 8 + warp;
    if (n >= NN) return;

    float xv[6];
    #pragma unroll
    for (int k = 0; k < 6; k++) xv[k] = x[n * 6 + k];
    float h0 = b1[lane], h1 = b1[lane + 32];
    #pragma unroll
    for (int k = 0; k < 6; k++) {
        h0 += xv[k] * w1[k * HIDN + lane];
        h1 += xv[k] * w1[k * HIDN + lane + 32];
    }
    h0 = fmaxf(h0, 0.f); h1 = fmaxf(h1, 0.f);

    float a0 = b2[lane], a1 = b2[lane + 32];
    #pragma unroll
    for (int k = 0; k < HIDN; k++) {
        float hk = (k < 32) ? __shfl_sync(0xffffffffu, h0, k)
                            : __shfl_sync(0xffffffffu, h1, k - 32);
        a0 += hk * w2s[k * HIDN + lane];
        a1 += hk * w2s[k * HIDN + lane + 32];
    }
    g_h[n * HIDN + lane]      = a0;
    g_h[n * HIDN + lane + 32] = a1;

    // transform for layer 0
    float t0 = 0.f, t1 = 0.f;
    #pragma unroll
    for (int k = 0; k < HIDN; k++) {
        float hk = (k < 32) ? __shfl_sync(0xffffffffu, a0, k)
                            : __shfl_sync(0xffffffffu, a1, k - 32);
        t0 += hk * wgs[k * HIDN + lane];
        t1 += hk * wgs[k * HIDN + lane + 32];
    }
    g_hw0[n * HIDN + lane]      = t0;
    g_hw0[n * HIDN + lane + 32] = t1;

    float rs0 = t0 * sa[lane], rs1 = t1 * sa[lane + 32];
    float rd0 = t0 * sd[lane], rd1 = t1 * sd[lane + 32];
    #pragma unroll
    for (int o = 8; o >= 1; o >>= 1) {
        rs0 += __shfl_xor_sync(0xffffffffu, rs0, o);
        rs1 += __shfl_xor_sync(0xffffffffu, rs1, o);
        rd0 += __shfl_xor_sync(0xffffffffu, rd0, o);
        rd1 += __shfl_xor_sync(0xffffffffu, rd1, o);
    }
    if (lane == 0)  { g_as0[n*NHD+0] = rs0; g_as0[n*NHD+2] = rs1;
                      g_ad0[n*NHD+0] = rd0; g_ad0[n*NHD+2] = rd1; }
    if (lane == 16) { g_as0[n*NHD+1] = rs0; g_as0[n*NHD+3] = rs1;
                      g_ad0[n*NHD+1] = rd0; g_ad0[n*NHD+3] = rd1; }
}

// ---------------------------------------------------------------------------
// Fused GAT layer: one warp per destination node. Walk CSR edges, accumulate
// softmax numerator (64 ch) + denominators in registers, then normalize +
// bias + ELU + residual + LayerNorm, then project with Wn:
//   last=0: hw_out = h_new @ Wn, head dots -> as_out/ad_out
//   last=1: outp  = h_new @ Wn + bn
// ---------------------------------------------------------------------------
__global__ void k_gat(const float* __restrict__ hw_in,
                      const float* __restrict__ as_in, const float* __restrict__ ad_in,
                      int l,
                      const float* __restrict__ b_gat,
                      const float* __restrict__ lng, const float* __restrict__ lnb,
                      const float* __restrict__ Wn,
                      const float* __restrict__ atts, const float* __restrict__ attd,
                      const float* __restrict__ bn,
                      float* __restrict__ hw_out,
                      float* __restrict__ as_out, float* __restrict__ ad_out,
                      float* __restrict__ outp, int last)
{
    __shared__ float ws[HIDN * HIDN];
    __shared__ float sa[HIDN], sd[HIDN];
    int tid = threadIdx.x;
    for (int i = tid; i < HIDN * HIDN / 4; i += blockDim.x)
        ((float4*)ws)[i] = ((const float4*)Wn)[i];
    if (!last && tid < HIDN) { sa[tid] = atts[tid]; sd[tid] = attd[tid]; }
    __syncthreads();

    int warp = tid >> 5, lane = tid & 31;
    int n = blockIdx.x * 8 + warp;
    if (n >= NN) return;

    int hd   = lane & 3;                     // score head for this lane
    int eidx = lane >> 2;                    // score edge slot (0..7)
    float c1h = g_c1[l * NHD + hd], c0h = g_c0[l * NHD + hd];
    float adh = ad_in[n * NHD + hd];
    int base = g_rs[n], dg = g_deg[n];

    float acc0 = 0.f, acc1 = 0.f, den = 0.f;
    int h0sel = lane >> 4;                   // head of channel `lane`   (0/1)
    for (int off = 0; off < dg; off += 8) {
        int m = dg - off; if (m > 8) m = 8;
        int   srcl = 0;
        float ex   = 0.f;
        if (eidx < m) {
            srcl = g_csrc[base + off + eidx];
            float eav = g_cea[base + off + eidx];
            float s = as_in[srcl * NHD + hd] + adh + eav * c1h + c0h;
            s = (s > 0.f) ? s : 0.2f * s;
            ex = __expf(s);
        }
        den += ex;
        for (int j = 0; j < m; j++) {
            int   sj = __shfl_sync(0xffffffffu, srcl, j * 4);
            float e0 = __shfl_sync(0xffffffffu, ex, j * 4 + h0sel);
            float e1 = __shfl_sync(0xffffffffu, ex, j * 4 + 2 + h0sel);
            acc0 += e0 * hw_in[sj * HIDN + lane];
            acc1 += e1 * hw_in[sj * HIDN + lane + 32];
        }
    }
    // reduce den across edge slots (lanes sharing lane&3)
    den += __shfl_xor_sync(0xffffffffu, den, 4);
    den += __shfl_xor_sync(0xffffffffu, den, 8);
    den += __shfl_xor_sync(0xffffffffu, den, 16);
    float den0 = __shfl_sync(0xffffffffu, den, h0sel);       // head h0sel (lane h0sel holds it)
    float den1 = __shfl_sync(0xffffffffu, den, 2 + h0sel);

    float v0 = acc0 / (den0 + 1e-16f) + b_gat[l * HIDN + lane];
    float v1 = acc1 / (den1 + 1e-16f) + b_gat[l * HIDN + lane + 32];
    v0 = (v0 > 0.f) ? v0 : expm1f(v0);
    v1 = (v1 > 0.f) ? v1 : expm1f(v1);

    float x0 = g_h[n * HIDN + lane]      + v0;
    float x1 = g_h[n * HIDN + lane + 32] + v1;

    float s = x0 + x1;
    #pragma unroll
    for (int o = 16; o; o >>= 1) s += __shfl_xor_sync(0xffffffffu, s, o);
    float mean = s * (1.f / 64.f);
    float vv = (x0 - mean) * (x0 - mean) + (x1 - mean) * (x1 - mean);
    #pragma unroll
    for (int o = 16; o; o >>= 1) vv += __shfl_xor_sync(0xffffffffu, vv, o);
    float inv = rsqrtf(vv * (1.f / 64.f) + 1e-5f);

    float h0n = (x0 - mean) * inv * lng[l * HIDN + lane]      + lnb[l * HIDN + lane];
    float h1n = (x1 - mean) * inv * lng[l * HIDN + lane + 32] + lnb[l * HIDN + lane + 32];
    if (!last) {                             // last layer: g_h no longer needed
        g_h[n * HIDN + lane]      = h0n;
        g_h[n * HIDN + lane + 32] = h1n;
    }

    // projection with ws (next-layer transform, or output projection)
    float a0 = last ? bn[lane]      : 0.f;
    float a1 = last ? bn[lane + 32] : 0.f;
    #pragma unroll
    for (int k = 0; k < HIDN; k++) {
        float hk = (k < 32) ? __shfl_sync(0xffffffffu, h0n, k)
                            : __shfl_sync(0xffffffffu, h1n, k - 32);
        a0 += hk * ws[k * HIDN + lane];
        a1 += hk * ws[k * HIDN + lane + 32];
    }
    if (last) {
        outp[n * HIDN + lane]      = a0;
        outp[n * HIDN + lane + 32] = a1;
        return;
    }
    hw_out[n * HIDN + lane]      = a0;
    hw_out[n * HIDN + lane + 32] = a1;

    float rs0 = a0 * sa[lane], rs1 = a1 * sa[lane + 32];
    float rd0 = a0 * sd[lane], rd1 = a1 * sd[lane + 32];
    #pragma unroll
    for (int o = 8; o >= 1; o >>= 1) {
        rs0 += __shfl_xor_sync(0xffffffffu, rs0, o);
        rs1 += __shfl_xor_sync(0xffffffffu, rs1, o);
        rd0 += __shfl_xor_sync(0xffffffffu, rd0, o);
        rd1 += __shfl_xor_sync(0xffffffffu, rd1, o);
    }
    if (lane == 0)  { as_out[n*NHD+0] = rs0; as_out[n*NHD+2] = rs1;
                      ad_out[n*NHD+0] = rd0; ad_out[n*NHD+2] = rd1; }
    if (lane == 16) { as_out[n*NHD+1] = rs0; as_out[n*NHD+3] = rs1;
                      ad_out[n*NHD+1] = rd0; ad_out[n*NHD+3] = rd1; }
}

// ---------------------------------------------------------------------------
extern "C" void kernel_launch(void* const* d_in, const int* in_sizes, int n_in,
                              void* d_out, int out_size)
{
    const float* x        = (const float*)d_in[0];
    const int*   ei       = (const int*)d_in[1];     // int64 in ref -> int32 on device
    const float* ea       = (const float*)d_in[2];
    const float* w_ne1    = (const float*)d_in[3];
    const float* b_ne1    = (const float*)d_in[4];
    const float* w_ne2    = (const float*)d_in[5];
    const float* b_ne2    = (const float*)d_in[6];
    const float* w_ee     = (const float*)d_in[7];
    const float* b_ee     = (const float*)d_in[8];
    const float* w_gat    = (const float*)d_in[9];
    const float* w_eg     = (const float*)d_in[10];
    const float* att_src  = (const float*)d_in[11];
    const float* att_dst  = (const float*)d_in[12];
    const float* att_edge = (const float*)d_in[13];
    const float* b_gat    = (const float*)d_in[14];
    const float* ln_g     = (const float*)d_in[15];
    const float* ln_b     = (const float*)d_in[16];
    const float* w_out    = (const float*)d_in[17];
    const float* b_out    = (const float*)d_in[18];
    float*       out      = (float*)d_out;

    int nb = (NN + 7) / 8;
    int eb = (EE + 255) / 256;

    float* g_hw0p;  cudaGetSymbolAddress((void**)&g_hw0p, g_hw0);
    float* g_hw1p;  cudaGetSymbolAddress((void**)&g_hw1p, g_hw1);
    float* g_as0p;  cudaGetSymbolAddress((void**)&g_as0p, g_as0);
    float* g_ad0p;  cudaGetSymbolAddress((void**)&g_ad0p, g_ad0);
    float* g_as1p;  cudaGetSymbolAddress((void**)&g_as1p, g_as1);
    float* g_ad1p;  cudaGetSymbolAddress((void**)&g_ad1p, g_ad1);

    k_const<<<NLY, HIDN>>>(w_ee, b_ee, w_eg, att_edge);

    // CSR build (amortized over 3 layers)
    k_zero<<<(NN + 255) / 256, 256>>>();
    k_count<<<eb, 256>>>(ei);
    k_scan1<<<SCAN_G, SCAN_B>>>();
    k_scan2<<<1, 128>>>();
    k_scan3<<<SCAN_G, SCAN_B>>>();
    k_scatter<<<eb, 256>>>(ei, ea);

    k_encode_t<<<nb, 256>>>(x, w_ne1, b_ne1, w_ne2, b_ne2,
                            w_gat, att_src, att_dst);

    // layer 0: read hw0 -> write hw1
    k_gat<<<nb, 256>>>(g_hw0p, g_as0p, g_ad0p, 0, b_gat, ln_g, ln_b,
                       w_gat + 1 * HIDN * HIDN,
                       att_src + 1 * NHD * DHD, att_dst + 1 * NHD * DHD,
                       nullptr, g_hw1p, g_as1p, g_ad1p, nullptr, 0);
    // layer 1: read hw1 -> write hw0
    k_gat<<<nb, 256>>>(g_hw1p, g_as1p, g_ad1p, 1, b_gat, ln_g, ln_b,
                       w_gat + 2 * HIDN * HIDN,
                       att_src + 2 * NHD * DHD, att_dst + 2 * NHD * DHD,
                       nullptr, g_hw0p, g_as0p, g_ad0p, nullptr, 0);
    // layer 2 (last): read hw0 -> out = h @ w_out + b_out
    k_gat<<<nb, 256>>>(g_hw0p, g_as0p, g_ad0p, 2, b_gat, ln_g, ln_b,
                       w_out, nullptr, nullptr, b_out,
                       nullptr, nullptr, nullptr, out, 1);
}